// round 10
// baseline (speedup 1.0000x reference)
#include <cuda_runtime.h>
#include <math.h>
#include <stdint.h>

typedef unsigned long long u64;

// ---- scratch (static device globals; no allocation) ----
__device__ __align__(16) float d_XE[(size_t)64 * 32 * 10 * 1024];  // 80MB  [t][b][p][h]
__device__ __align__(16) float d_h[32 * 1024];                     // [b][h]
__device__ __align__(16) float d_c[32 * 1024];                     // [b][h]
__device__ __align__(16) float d_hT[1024 * 32];                    // [h][b]
__device__ __align__(16) float d_embT[1024 * 32];                  // [i][b]
__device__ __align__(16) float d_g2T[4096 * 32];                   // [j][b]
__device__ __align__(16) float d_hWhT[1024 * 32];                  // [h][b]
__device__ __align__(16) float d_WrecB[640 * 8192];                // 20MB blocked [tile][k][8]
__device__ __align__(16) float d_WihB[512 * 8192];                 // 16MB blocked [tile][k][8]
// grid barrier: counter and generation on SEPARATE 128B cache lines
__device__ __align__(128) unsigned d_barc[32];                     // [0] = arrival count
__device__ __align__(128) unsigned d_barg[32];                     // [0] = generation

// ---- f32x2 helpers ----
static __device__ __forceinline__ u64 dup2f(float a) {
    u64 r; asm("mov.b64 %0,{%1,%1};" : "=l"(r) : "f"(a)); return r;
}
static __device__ __forceinline__ void ffma2(u64& d, u64 a, u64 b) {
    asm("fma.rn.f32x2 %0,%1,%2,%0;" : "+l"(d) : "l"(a), "l"(b));
}
static __device__ __forceinline__ void unpack2(u64 v, float& a, float& b) {
    asm("mov.b64 {%0,%1},%2;" : "=f"(a), "=f"(b) : "l"(v));
}
static __device__ __forceinline__ float sigf(float x) { return 1.0f / (1.0f + expf(-x)); }

// ---- sub-block (256-thread) named barrier ----
static __device__ __forceinline__ void barsub(int nb) {
    asm volatile("bar.sync %0, %1;" :: "r"(nb), "r"(256) : "memory");
}

// ---- software grid barrier (all blocks resident; padded lines + backoff spin) ----
static __device__ __forceinline__ void gridbar() {
    __syncthreads();
    if (threadIdx.x == 0) {
        __threadfence();
        unsigned g = *(volatile unsigned*)&d_barg[0];
        if (atomicAdd(&d_barc[0], 1u) == gridDim.x - 1) {
            d_barc[0] = 0;
            __threadfence();
            *(volatile unsigned*)&d_barg[0] = g + 1;
        } else {
            while (*(volatile unsigned*)&d_barg[0] == g) { __nanosleep(64); }
            __threadfence();
        }
    }
    __syncthreads();
}

// ---- init: zero recurrent state ----
__global__ void k_init() {
    int i = blockIdx.x * blockDim.x + threadIdx.x;   // 512*256 = 131072
    d_g2T[i] = 0.0f;
    if (i < 32 * 1024) { d_c[i] = 0.0f; d_hWhT[i] = 0.0f; }
}

// ---- prep: blocked transpose of [Whh;Wh] -> WrecB[tile][k][s], j = tile*8+s ----
__global__ __launch_bounds__(256) void k_prep_rec(const float* __restrict__ Whh,
                                                  const float* __restrict__ Wh) {
    __shared__ __align__(16) float sm[32][36];
    const int tid = threadIdx.x;
    const int k0 = blockIdx.x * 32, jt = blockIdx.y;
    {
        int r = tid >> 3, c4 = (tid & 7) * 4;
        int j = jt * 32 + r;
        const float* src = (j < 4096) ? (Whh + (size_t)j * 1024) : (Wh + (size_t)(j - 4096) * 1024);
        *(float4*)&sm[r][c4] = *(const float4*)&src[k0 + c4];
    }
    __syncthreads();
    int kk = tid >> 3, s = tid & 7;
#pragma unroll
    for (int bji = 0; bji < 4; bji++) {
        d_WrecB[(size_t)(jt * 4 + bji) * 8192 + (k0 + kk) * 8 + s] = sm[bji * 8 + s][kk];
    }
}

// ---- prep: blocked transpose of Wih -> WihB[tile][k][s], s=(g,hh): j=g*1024+tile*2+hh ----
__global__ __launch_bounds__(256) void k_prep_ih(const float* __restrict__ Wih) {
    __shared__ __align__(16) float sm[32][36];
    const int tid = threadIdx.x;
    const int k0 = blockIdx.x * 32, grp = blockIdx.y;
    {
        int r = tid >> 3, c4 = (tid & 7) * 4;
        int g = r >> 3, bji = (r & 7) >> 1, hh = r & 1;
        int j = g * 1024 + (grp * 4 + bji) * 2 + hh;
        *(float4*)&sm[r][c4] = *(const float4*)&Wih[(size_t)j * 1024 + k0 + c4];
    }
    __syncthreads();
    int kk = tid >> 3, s = tid & 7;
    int g = s >> 1, hh = s & 1;
#pragma unroll
    for (int bji = 0; bji < 4; bji++) {
        d_WihB[(size_t)(grp * 4 + bji) * 8192 + (k0 + kk) * 8 + s] = sm[g * 8 + bji * 2 + hh][kk];
    }
}

// ---- K0: XE[r][h] = x_row[r] . Wx[h],  r=(t,b,p)  M=20480 N=1024 K=1024 (SIMT f32x2) ----
__global__ __launch_bounds__(256) void k_xe(const float* __restrict__ x,
                                            const float* __restrict__ Wx) {
    __shared__ __align__(16) float As[16][132];
    __shared__ __align__(16) float Bs[16][132];
    __shared__ int Abase[128];
    const int tid = threadIdx.x;
    const int n0 = blockIdx.x * 128, m0 = blockIdx.y * 128;
    if (tid < 128) {
        int r = m0 + tid, t = r / 320, rem = r - t * 320, b = rem / 10, p = rem - b * 10;
        Abase[tid] = ((b * 64 + t) * 10 + p) * 1024;
    }
    __syncthreads();
    const int tm = tid >> 4, tn = tid & 15;
    u64 acc[8][4];
#pragma unroll
    for (int i = 0; i < 8; i++)
#pragma unroll
        for (int j = 0; j < 4; j++) acc[i][j] = 0ull;

    for (int k0 = 0; k0 < 1024; k0 += 16) {
#pragma unroll
        for (int l = 0; l < 2; l++) {
            int ii = tid + 256 * l, m = ii >> 2, c = ii & 3;
            float4 va = *(const float4*)&x[Abase[m] + k0 + c * 4];
            As[c * 4 + 0][m] = va.x; As[c * 4 + 1][m] = va.y;
            As[c * 4 + 2][m] = va.z; As[c * 4 + 3][m] = va.w;
            float4 vb = *(const float4*)&Wx[(size_t)(n0 + m) * 1024 + k0 + c * 4];
            Bs[c * 4 + 0][m] = vb.x; Bs[c * 4 + 1][m] = vb.y;
            Bs[c * 4 + 2][m] = vb.z; Bs[c * 4 + 3][m] = vb.w;
        }
        __syncthreads();
#pragma unroll
        for (int kk = 0; kk < 16; kk++) {
            float4 alo = *(const float4*)&As[kk][tm * 8];
            float4 ahi = *(const float4*)&As[kk][tm * 8 + 4];
            ulonglong2 bl = *(const ulonglong2*)&Bs[kk][tn * 8];
            ulonglong2 bh = *(const ulonglong2*)&Bs[kk][tn * 8 + 4];
            float a8[8] = {alo.x, alo.y, alo.z, alo.w, ahi.x, ahi.y, ahi.z, ahi.w};
#pragma unroll
            for (int r = 0; r < 8; r++) {
                u64 ad = dup2f(a8[r]);
                ffma2(acc[r][0], ad, bl.x); ffma2(acc[r][1], ad, bl.y);
                ffma2(acc[r][2], ad, bh.x); ffma2(acc[r][3], ad, bh.y);
            }
        }
        __syncthreads();
    }
#pragma unroll
    for (int r = 0; r < 8; r++) {
        float o[8];
        unpack2(acc[r][0], o[0], o[1]); unpack2(acc[r][1], o[2], o[3]);
        unpack2(acc[r][2], o[4], o[5]); unpack2(acc[r][3], o[6], o[7]);
        size_t row = (size_t)(m0 + tm * 8 + r);
        *(float4*)&d_XE[row * 1024 + n0 + tn * 8]     = make_float4(o[0], o[1], o[2], o[3]);
        *(float4*)&d_XE[row * 1024 + n0 + tn * 8 + 4] = make_float4(o[4], o[5], o[6], o[7]);
    }
}

// ==== persistent recurrence kernel: 148 blocks x 512 threads, dyn smem 84KB ====
// per-sub (256 thr) smem: ws[1024][8] (32KB) + ps[8][8][32] (8KB) + gvs[8][32] (1KB)
#define SUB_BYTES 41984

__global__ __launch_bounds__(512) void k_loop(const float* __restrict__ x,
                                              const float* __restrict__ b_att,
                                              const float* __restrict__ v,
                                              const float* __restrict__ bih,
                                              const float* __restrict__ bhh,
                                              const float* __restrict__ Wfc,
                                              const float* __restrict__ bfc,
                                              float* __restrict__ out) {
    extern __shared__ __align__(16) char dsm[];
    __shared__ float s_att[10][17];
    __shared__ float s_al[10];
    const int tid = threadIdx.x, bid = blockIdx.x;
    const int subl = tid >> 8;            // 0/1 within block
    const int stid = tid & 255;
    const int nb = 1 + subl;              // named barrier id
    const int sub = bid * 2 + subl;       // global sub id, [0,296)
    float (*ws)[8]      = (float(*)[8])(dsm + subl * SUB_BYTES);
    float (*ps)[8][32]  = (float(*)[8][32])(dsm + subl * SUB_BYTES + 32768);
    float (*gvs)[32]    = (float(*)[32])(dsm + subl * SUB_BYTES + 32768 + 8192);
    const int w = stid >> 5, lane = stid & 31;

    for (int t = 0; t < 64; t++) {
        // ---- phase A: attention (blocks 0..31, one b each) ----
        if (bid < 32) {
            const int b = bid;
            const float* xe = d_XE + (size_t)(t * 32 + b) * 10240;
            float psc[10];
#pragma unroll
            for (int p = 0; p < 10; p++) psc[p] = 0.0f;
#pragma unroll
            for (int hh = 0; hh < 2; hh++) {
                int h = tid + hh * 512;
                float base = d_hWhT[h * 32 + b] + b_att[h];
                float vh = v[h];
#pragma unroll
                for (int p = 0; p < 10; p++)
                    psc[p] = fmaf(tanhf(xe[p * 1024 + h] + base), vh, psc[p]);
            }
            const int fl = tid & 31, fw = tid >> 5;
#pragma unroll
            for (int p = 0; p < 10; p++) {
                float s = psc[p];
#pragma unroll
                for (int off = 16; off; off >>= 1) s += __shfl_xor_sync(0xffffffffu, s, off);
                if (fl == 0) s_att[p][fw] = s;
            }
            __syncthreads();
            if (tid == 0) {
                float sc[10], mx = -1e30f;
#pragma unroll
                for (int p = 0; p < 10; p++) {
                    float s = 0.0f;
#pragma unroll
                    for (int q = 0; q < 16; q++) s += s_att[p][q];
                    sc[p] = s; mx = fmaxf(mx, s);
                }
                float den = 0.0f;
#pragma unroll
                for (int p = 0; p < 10; p++) { sc[p] = expf(sc[p] - mx); den += sc[p]; }
                float inv = 1.0f / den;
#pragma unroll
                for (int p = 0; p < 10; p++) s_al[p] = sc[p] * inv;
            }
            __syncthreads();
            float a[10];
#pragma unroll
            for (int p = 0; p < 10; p++) a[p] = s_al[p];
            const float* xb = x + (size_t)(b * 64 + t) * 10240;
#pragma unroll
            for (int hh = 0; hh < 2; hh++) {
                int i = tid + hh * 512;
                float s = 0.0f;
#pragma unroll
                for (int p = 0; p < 10; p++) s = fmaf(a[p], xb[p * 1024 + i], s);
                d_embT[i * 32 + b] = s;
            }
        }
        gridbar();

        // ---- phase B: gates GEMM + fused LSTM cell (512 tiles over 296 subs) ----
        for (int tl = sub; tl < 512; tl += 296) {
            const float4* wb = (const float4*)(d_WihB + (size_t)tl * 8192);
#pragma unroll
            for (int i = 0; i < 8; i++) ((float4*)ws)[stid + i * 256] = wb[stid + i * 256];
            barsub(nb);
            u64 acc[4] = {0ull, 0ull, 0ull, 0ull};
            const float* eb = d_embT + w * 128 * 32 + lane;
#pragma unroll 4
            for (int k = 0; k < 128; k++) {
                u64 ed = dup2f(eb[k * 32]);
                int kk = w * 128 + k;
                ulonglong2 w01 = *(const ulonglong2*)&ws[kk][0];
                ulonglong2 w23 = *(const ulonglong2*)&ws[kk][4];
                ffma2(acc[0], ed, w01.x); ffma2(acc[1], ed, w01.y);
                ffma2(acc[2], ed, w23.x); ffma2(acc[3], ed, w23.y);
            }
#pragma unroll
            for (int q = 0; q < 4; q++) {
                float a2, b2; unpack2(acc[q], a2, b2);
                ps[w][2 * q][lane] = a2; ps[w][2 * q + 1][lane] = b2;
            }
            barsub(nb);
            {
                const int s = w, b = lane;
                float r = 0.0f;
#pragma unroll
                for (int q = 0; q < 8; q++) r += ps[q][s][b];
                int g = s >> 1, hh = s & 1;
                int j = g * 1024 + tl * 2 + hh;
                r += d_g2T[j * 32 + b] + bih[j] + bhh[j];
                gvs[s][b] = r;
            }
            barsub(nb);
            if (stid < 64) {
                int b = stid >> 1, hh = stid & 1;
                int h = tl * 2 + hh;
                float iv = gvs[0 + hh][b], fv = gvs[2 + hh][b];
                float gv = gvs[4 + hh][b], ov = gvs[6 + hh][b];
                float c = d_c[b * 1024 + h];
                float cn = sigf(fv) * c + sigf(iv) * tanhf(gv);
                float hn = sigf(ov) * tanhf(cn);
                d_c[b * 1024 + h] = cn;
                d_h[b * 1024 + h] = hn;
                d_hT[h * 32 + b] = hn;
            }
        }
        gridbar();

        // ---- phase C: rec GEMM h @ [Whh;Wh]^T (640 tiles over 296 subs) ----
        if (t < 63) {
            for (int tl = sub; tl < 640; tl += 296) {
                const float4* wb = (const float4*)(d_WrecB + (size_t)tl * 8192);
#pragma unroll
                for (int i = 0; i < 8; i++) ((float4*)ws)[stid + i * 256] = wb[stid + i * 256];
                barsub(nb);
                u64 acc[4] = {0ull, 0ull, 0ull, 0ull};
                const float* eb = d_hT + w * 128 * 32 + lane;
#pragma unroll 4
                for (int k = 0; k < 128; k++) {
                    u64 ed = dup2f(eb[k * 32]);
                    int kk = w * 128 + k;
                    ulonglong2 w01 = *(const ulonglong2*)&ws[kk][0];
                    ulonglong2 w23 = *(const ulonglong2*)&ws[kk][4];
                    ffma2(acc[0], ed, w01.x); ffma2(acc[1], ed, w01.y);
                    ffma2(acc[2], ed, w23.x); ffma2(acc[3], ed, w23.y);
                }
#pragma unroll
                for (int q = 0; q < 4; q++) {
                    float a2, b2; unpack2(acc[q], a2, b2);
                    ps[w][2 * q][lane] = a2; ps[w][2 * q + 1][lane] = b2;
                }
                barsub(nb);
                {
                    const int s = w, b = lane;
                    float r = 0.0f;
#pragma unroll
                    for (int q = 0; q < 8; q++) r += ps[q][s][b];
                    int j = tl * 8 + s;
                    if (j < 4096) d_g2T[j * 32 + b] = r;
                    else          d_hWhT[(j - 4096) * 32 + b] = r;
                }
                barsub(nb);
            }
            gridbar();
        }
    }

    // ---- final FC (blocks 0..31) ----
    if (bid < 32 && tid < 256) {
        const int b = bid, fw = tid >> 5, fl = tid & 31;
        if (fw < 8) {
            const float* hr = d_h + b * 1024;
            const float* wr = Wfc + fw * 1024;
            float s = 0.0f;
            for (int i = fl * 4; i < 1024; i += 128) {
                float4 hv = *(const float4*)&hr[i];
                float4 wv = *(const float4*)&wr[i];
                s = fmaf(hv.x, wv.x, s); s = fmaf(hv.y, wv.y, s);
                s = fmaf(hv.z, wv.z, s); s = fmaf(hv.w, wv.w, s);
            }
#pragma unroll
            for (int off = 16; off; off >>= 1) s += __shfl_xor_sync(0xffffffffu, s, off);
            if (fl == 0) out[b * 8 + fw] = s + bfc[fw];
        }
    }
}

extern "C" void kernel_launch(void* const* d_in, const int* in_sizes, int n_in,
                              void* d_out, int out_size) {
    const float* x     = (const float*)d_in[0];
    const float* Wx    = (const float*)d_in[1];
    const float* Wh    = (const float*)d_in[2];
    const float* b_att = (const float*)d_in[3];
    const float* v     = (const float*)d_in[4];
    const float* Wih   = (const float*)d_in[5];
    const float* Whh   = (const float*)d_in[6];
    const float* bih   = (const float*)d_in[7];
    const float* bhh   = (const float*)d_in[8];
    const float* Wfc   = (const float*)d_in[9];
    const float* bfc   = (const float*)d_in[10];
    float* out = (float*)d_out;

    static int attr_set = 0;
    if (!attr_set) {
        cudaFuncSetAttribute(k_loop, cudaFuncAttributeMaxDynamicSharedMemorySize,
                             2 * SUB_BYTES);
        attr_set = 1;
    }

    k_init<<<512, 256>>>();
    k_prep_rec<<<dim3(32, 160), 256>>>(Whh, Wh);
    k_prep_ih<<<dim3(32, 128), 256>>>(Wih);
    k_xe<<<dim3(8, 160), 256>>>(x, Wx);
    k_loop<<<148, 512, 2 * SUB_BYTES>>>(x, b_att, v, bih, bhh, Wfc, bfc, out);
}

// round 11
// speedup vs baseline: 1.3980x; 1.3980x over previous
#include <cuda_runtime.h>
#include <cuda_bf16.h>
#include <math.h>
#include <stdint.h>

typedef unsigned long long u64;

// ---- scratch (static device globals; no allocation) ----
__device__ __align__(16) float d_XE[(size_t)64 * 32 * 10 * 1024];  // 80MB  [t][b][p][h] = [r][h]
__device__ __align__(16) float d_h[32 * 1024];                     // [b][h]
__device__ __align__(16) float d_c[32 * 1024];                     // [b][h]
__device__ __align__(16) float d_hT[1024 * 32];                    // [h][b]
__device__ __align__(16) float d_embT[1024 * 32];                  // [i][b]
__device__ __align__(16) float d_g2T[4096 * 32];                   // [j][b]
__device__ __align__(16) float d_hWhT[1024 * 32];                  // [h][b]
__device__ __align__(16) float d_WrecB[640 * 8192];                // 20MB blocked [tile][k][8]
__device__ __align__(16) float d_WihB[512 * 8192];                 // 16MB blocked [tile][k][8]
__device__ __align__(16) __nv_bfloat16 d_A2[(size_t)20480 * 2048]; // 80MB [r][hi(1024)|lo(1024)]
__device__ __align__(16) __nv_bfloat16 d_B2T[(size_t)2048 * 1024]; // 4MB  [k: hi|lo][h]

// ---- f32x2 helpers ----
static __device__ __forceinline__ u64 dup2f(float a) {
    u64 r; asm("mov.b64 %0,{%1,%1};" : "=l"(r) : "f"(a)); return r;
}
static __device__ __forceinline__ void ffma2(u64& d, u64 a, u64 b) {
    asm("fma.rn.f32x2 %0,%1,%2,%0;" : "+l"(d) : "l"(a), "l"(b));
}
static __device__ __forceinline__ void unpack2(u64 v, float& a, float& b) {
    asm("mov.b64 {%0,%1},%2;" : "=f"(a), "=f"(b) : "l"(v));
}
static __device__ __forceinline__ float sigf(float x) { return 1.0f / (1.0f + expf(-x)); }

// ---- mma.sync helpers (base PTX, compute_103-safe) ----
static __device__ __forceinline__ uint32_t s2u(const void* p) {
    uint32_t a;
    asm("{ .reg .u64 t; cvta.to.shared.u64 t, %1; cvt.u32.u64 %0, t; }" : "=r"(a) : "l"(p));
    return a;
}
static __device__ __forceinline__ void ldsm4(uint32_t* r, uint32_t addr) {
    asm volatile("ldmatrix.sync.aligned.m8n8.x4.shared.b16 {%0,%1,%2,%3},[%4];"
                 : "=r"(r[0]), "=r"(r[1]), "=r"(r[2]), "=r"(r[3]) : "r"(addr));
}
static __device__ __forceinline__ void ldsm4t(uint32_t* r, uint32_t addr) {
    asm volatile("ldmatrix.sync.aligned.m8n8.x4.trans.shared.b16 {%0,%1,%2,%3},[%4];"
                 : "=r"(r[0]), "=r"(r[1]), "=r"(r[2]), "=r"(r[3]) : "r"(addr));
}
static __device__ __forceinline__ void mma16816(float* d, const uint32_t* a, const uint32_t* b) {
    asm volatile(
        "mma.sync.aligned.m16n8k16.row.col.f32.bf16.bf16.f32 "
        "{%0,%1,%2,%3},{%4,%5,%6,%7},{%8,%9},{%0,%1,%2,%3};"
        : "+f"(d[0]), "+f"(d[1]), "+f"(d[2]), "+f"(d[3])
        : "r"(a[0]), "r"(a[1]), "r"(a[2]), "r"(a[3]), "r"(b[0]), "r"(b[1]));
}

// ---- init: zero recurrent state ----
__global__ void k_init() {
    int i = blockIdx.x * blockDim.x + threadIdx.x;   // 512*256 = 131072
    d_g2T[i] = 0.0f;
    if (i < 32 * 1024) { d_c[i] = 0.0f; d_hWhT[i] = 0.0f; }
}

// ---- prep: blocked transpose of [Whh;Wh] -> WrecB[tile][k][s], j = tile*8+s ----
__global__ __launch_bounds__(256) void k_prep_rec(const float* __restrict__ Whh,
                                                  const float* __restrict__ Wh) {
    __shared__ __align__(16) float sm[32][36];
    const int tid = threadIdx.x;
    const int k0 = blockIdx.x * 32, jt = blockIdx.y;
    {
        int r = tid >> 3, c4 = (tid & 7) * 4;
        int j = jt * 32 + r;
        const float* src = (j < 4096) ? (Whh + (size_t)j * 1024) : (Wh + (size_t)(j - 4096) * 1024);
        *(float4*)&sm[r][c4] = *(const float4*)&src[k0 + c4];
    }
    __syncthreads();
    int kk = tid >> 3, s = tid & 7;
#pragma unroll
    for (int bji = 0; bji < 4; bji++) {
        d_WrecB[(size_t)(jt * 4 + bji) * 8192 + (k0 + kk) * 8 + s] = sm[bji * 8 + s][kk];
    }
}

// ---- prep: blocked transpose of Wih -> WihB[tile][k][s], s=(g,hh): j=g*1024+tile*2+hh ----
__global__ __launch_bounds__(256) void k_prep_ih(const float* __restrict__ Wih) {
    __shared__ __align__(16) float sm[32][36];
    const int tid = threadIdx.x;
    const int k0 = blockIdx.x * 32, grp = blockIdx.y;
    {
        int r = tid >> 3, c4 = (tid & 7) * 4;
        int g = r >> 3, bji = (r & 7) >> 1, hh = r & 1;
        int j = g * 1024 + (grp * 4 + bji) * 2 + hh;
        *(float4*)&sm[r][c4] = *(const float4*)&Wih[(size_t)j * 1024 + k0 + c4];
    }
    __syncthreads();
    int kk = tid >> 3, s = tid & 7;
    int g = s >> 1, hh = s & 1;
#pragma unroll
    for (int bji = 0; bji < 4; bji++) {
        d_WihB[(size_t)(grp * 4 + bji) * 8192 + (k0 + kk) * 8 + s] = sm[g * 8 + bji * 2 + hh][kk];
    }
}

// ---- cvt: x -> A2 bf16 hi/lo, gathered to r=(t,b,p) row order ----
__global__ __launch_bounds__(256) void k_cvt_x(const float* __restrict__ x) {
    const int B = blockIdx.x;                       // x-order row (b,t,p)
    const int b = B / 640, rem = B % 640, t = rem / 10, p = rem % 10;
    const size_t r = (size_t)(t * 320 + b * 10 + p);
    const int k4 = threadIdx.x * 4;
    float4 v = *(const float4*)(x + (size_t)B * 1024 + k4);
    __nv_bfloat162 hi01 = __floats2bfloat162_rn(v.x, v.y);
    __nv_bfloat162 hi23 = __floats2bfloat162_rn(v.z, v.w);
    float lx = v.x - __bfloat162float(__low2bfloat16(hi01));
    float ly = v.y - __bfloat162float(__high2bfloat16(hi01));
    float lz = v.z - __bfloat162float(__low2bfloat16(hi23));
    float lw = v.w - __bfloat162float(__high2bfloat16(hi23));
    __nv_bfloat162 lo01 = __floats2bfloat162_rn(lx, ly);
    __nv_bfloat162 lo23 = __floats2bfloat162_rn(lz, lw);
    *(__nv_bfloat162*)(d_A2 + r * 2048 + k4)            = hi01;
    *(__nv_bfloat162*)(d_A2 + r * 2048 + k4 + 2)        = hi23;
    *(__nv_bfloat162*)(d_A2 + r * 2048 + 1024 + k4)     = lo01;
    *(__nv_bfloat162*)(d_A2 + r * 2048 + 1024 + k4 + 2) = lo23;
}

// ---- cvt: Wx -> B2T transposed bf16 hi/lo: B2T[k][h] (hi rows 0-1023, lo 1024-2047) ----
__global__ __launch_bounds__(256) void k_cvt_w(const float* __restrict__ Wx) {
    __shared__ __align__(16) unsigned short s_hi[64][40];
    __shared__ __align__(16) unsigned short s_lo[64][40];
    const int tid = threadIdx.x;
    const int k0 = blockIdx.x * 64, h0 = blockIdx.y * 32;
    {
        int hl = tid >> 3, kq = (tid & 7) * 8;
        const float* src = Wx + (size_t)(h0 + hl) * 1024 + k0 + kq;
        float4 v0 = *(const float4*)src;
        float4 v1 = *(const float4*)(src + 4);
        float vv[8] = {v0.x, v0.y, v0.z, v0.w, v1.x, v1.y, v1.z, v1.w};
#pragma unroll
        for (int j = 0; j < 8; j++) {
            __nv_bfloat16 hb = __float2bfloat16_rn(vv[j]);
            float lo = vv[j] - __bfloat162float(hb);
            __nv_bfloat16 lb = __float2bfloat16_rn(lo);
            s_hi[kq + j][hl] = *(unsigned short*)&hb;
            s_lo[kq + j][hl] = *(unsigned short*)&lb;
        }
    }
    __syncthreads();
    int kl = tid >> 2, hq = (tid & 3) * 8;
    uint4 hv = *(const uint4*)&s_hi[kl][hq];
    uint4 lv = *(const uint4*)&s_lo[kl][hq];
    *(uint4*)(d_B2T + (size_t)(k0 + kl) * 1024 + h0 + hq)        = hv;
    *(uint4*)(d_B2T + (size_t)(1024 + k0 + kl) * 1024 + h0 + hq) = lv;
}

// ---- K0 via mma.sync bf16: XE = A2 x B2T, 3-segment split folded into K=3072 ----
// grid 1280 (m=bid>>3, n=bid&7), 256 thr, tile 128x128, 48 chunks of k=64, double buffer
#define SA_STRIDE 72               // bf16 units (144B rows)
#define SB_STRIDE 136              // bf16 units (272B rows)
#define SA_BYTES (128 * 144)       // 18432
#define SB_BYTES (64 * 272)        // 17408
#define XE_SMEM (2 * SA_BYTES + 2 * SB_BYTES)   // 71680

static __device__ __forceinline__ void xe_load_chunk(char* dsm, int buf, int c,
                                                     int m0, int n0, int tid) {
    const int seg = c >> 4, kc = (c & 15) << 6;
    const int aoff = (seg == 2) ? 1024 : 0;
    const int boff = (seg == 1) ? 1024 : 0;
    {   // A: 128 rows x 64 k; thread -> row=tid>>1, half=(tid&1)*32k (64B)
        int row = tid >> 1, half = tid & 1;
        const uint4* src = (const uint4*)(d_A2 + (size_t)(m0 + row) * 2048 + aoff + kc + half * 32);
        char* dst = dsm + buf * SA_BYTES + row * 144 + half * 64;
#pragma unroll
        for (int j = 0; j < 4; j++) *(uint4*)(dst + j * 16) = src[j];
    }
    {   // B: 64 k-rows x 128 n; thread -> row=tid>>2, q=(tid&3)*32n (64B)
        int row = tid >> 2, q = tid & 3;
        const uint4* src = (const uint4*)(d_B2T + (size_t)(boff + kc + row) * 1024 + n0 + q * 32);
        char* dst = dsm + 2 * SA_BYTES + buf * SB_BYTES + row * 272 + q * 64;
#pragma unroll
        for (int j = 0; j < 4; j++) *(uint4*)(dst + j * 16) = src[j];
    }
}

__global__ __launch_bounds__(256, 2) void k_xe_mma() {
    extern __shared__ __align__(16) char dsm[];
    const int tid = threadIdx.x, wid = tid >> 5, lane = tid & 31;
    const int m0 = (blockIdx.x >> 3) * 128, n0 = (blockIdx.x & 7) * 128;
    const int wm = wid >> 2, wn = wid & 3;           // warp tile: 64m x 32n
    const uint32_t smem0 = s2u(dsm);

    float acc[4][4][4];
#pragma unroll
    for (int i = 0; i < 4; i++)
#pragma unroll
        for (int j = 0; j < 4; j++)
#pragma unroll
            for (int q = 0; q < 4; q++) acc[i][j][q] = 0.0f;

    xe_load_chunk(dsm, 0, 0, m0, n0, tid);
    __syncthreads();

    for (int c = 0; c < 48; c++) {
        if (c + 1 < 48) xe_load_chunk(dsm, (c + 1) & 1, c + 1, m0, n0, tid);
        const uint32_t Ab = smem0 + (c & 1) * SA_BYTES;
        const uint32_t Bb = smem0 + 2 * SA_BYTES + (c & 1) * SB_BYTES;
        const uint32_t arow = (lane & 15), ahalf = (lane >> 4) * 8;
#pragma unroll
        for (int ks = 0; ks < 4; ks++) {
            const int kk = ks * 16;
            uint32_t a[4][4];
#pragma unroll
            for (int mt = 0; mt < 4; mt++)
                ldsm4(a[mt], Ab + (wm * 64 + mt * 16 + arow) * 144 + (kk + ahalf) * 2);
            uint32_t bfr[2][4];
#pragma unroll
            for (int pr = 0; pr < 2; pr++)
                ldsm4t(bfr[pr], Bb + (kk + arow) * 272 + (wn * 32 + pr * 16 + ahalf) * 2);
#pragma unroll
            for (int mt = 0; mt < 4; mt++) {
#pragma unroll
                for (int nt = 0; nt < 4; nt++) {
                    mma16816(acc[mt][nt], a[mt], &bfr[nt >> 1][(nt & 1) * 2]);
                }
            }
        }
        __syncthreads();
    }

    // epilogue: d-frag (row=lane>>2, col=2*(lane&3)); rows +8 for d2,d3
#pragma unroll
    for (int mt = 0; mt < 4; mt++) {
#pragma unroll
        for (int nt = 0; nt < 4; nt++) {
            int row = m0 + wm * 64 + mt * 16 + (lane >> 2);
            int col = n0 + wn * 32 + nt * 8 + (lane & 3) * 2;
            *(float2*)(d_XE + (size_t)row * 1024 + col) =
                make_float2(acc[mt][nt][0], acc[mt][nt][1]);
            *(float2*)(d_XE + (size_t)(row + 8) * 1024 + col) =
                make_float2(acc[mt][nt][2], acc[mt][nt][3]);
        }
    }
}

// ---- attn(t): scores -> softmax over P=10 -> pooled embT. one block per b ----
__global__ __launch_bounds__(256) void k_attn(int t, const float* __restrict__ x,
                                              const float* __restrict__ b_att,
                                              const float* __restrict__ v) {
    const int b = blockIdx.x, tid = threadIdx.x;
    __shared__ float part[10][8];
    __shared__ float al[10];
    float ps[10];
#pragma unroll
    for (int p = 0; p < 10; p++) ps[p] = 0.0f;
    const float* xe = d_XE + (size_t)(t * 32 + b) * 10 * 1024;
    for (int h = tid; h < 1024; h += 256) {
        float base = d_hWhT[h * 32 + b] + b_att[h];
        float vh = v[h];
#pragma unroll
        for (int p = 0; p < 10; p++) {
            float e = tanhf(xe[p * 1024 + h] + base);
            ps[p] = fmaf(e, vh, ps[p]);
        }
    }
    int lane = tid & 31, w = tid >> 5;
#pragma unroll
    for (int p = 0; p < 10; p++) {
        float s = ps[p];
#pragma unroll
        for (int off = 16; off; off >>= 1) s += __shfl_xor_sync(0xffffffffu, s, off);
        if (lane == 0) part[p][w] = s;
    }
    __syncthreads();
    if (tid == 0) {
        float sc[10], mx = -1e30f;
#pragma unroll
        for (int p = 0; p < 10; p++) {
            float s = 0.0f;
#pragma unroll
            for (int q = 0; q < 8; q++) s += part[p][q];
            sc[p] = s; mx = fmaxf(mx, s);
        }
        float den = 0.0f;
#pragma unroll
        for (int p = 0; p < 10; p++) { sc[p] = expf(sc[p] - mx); den += sc[p]; }
        float inv = 1.0f / den;
#pragma unroll
        for (int p = 0; p < 10; p++) al[p] = sc[p] * inv;
    }
    __syncthreads();
    float a[10];
#pragma unroll
    for (int p = 0; p < 10; p++) a[p] = al[p];
    const float* xb = x + (size_t)(b * 64 + t) * 10 * 1024;
    for (int i = tid; i < 1024; i += 256) {
        float s = 0.0f;
#pragma unroll
        for (int p = 0; p < 10; p++) s = fmaf(a[p], xb[p * 1024 + i], s);
        d_embT[i * 32 + b] = s;
    }
}

// ---- gates: 512 blocks. block bj -> h cols {bj*2, bj*2+1} x 4 gates. fused cell ----
__global__ __launch_bounds__(256) void k_gates(const float* __restrict__ bih,
                                               const float* __restrict__ bhh) {
    __shared__ __align__(16) float ws[1024][8];
    __shared__ float ps[8][8][32];
    __shared__ float gvs[8][32];
    const int tid = threadIdx.x, bj = blockIdx.x;
    const float4* wb = (const float4*)(d_WihB + (size_t)bj * 8192);
#pragma unroll
    for (int i = 0; i < 8; i++) ((float4*)ws)[tid + i * 256] = wb[tid + i * 256];
    __syncthreads();
    const int w = tid >> 5, lane = tid & 31;
    u64 acc[4] = {0ull, 0ull, 0ull, 0ull};
    const float* eb = d_embT + w * 128 * 32 + lane;
#pragma unroll 4
    for (int k = 0; k < 128; k++) {
        u64 ed = dup2f(eb[k * 32]);
        int kk = w * 128 + k;
        ulonglong2 w01 = *(const ulonglong2*)&ws[kk][0];
        ulonglong2 w23 = *(const ulonglong2*)&ws[kk][4];
        ffma2(acc[0], ed, w01.x); ffma2(acc[1], ed, w01.y);
        ffma2(acc[2], ed, w23.x); ffma2(acc[3], ed, w23.y);
    }
#pragma unroll
    for (int q = 0; q < 4; q++) {
        float a2, b2; unpack2(acc[q], a2, b2);
        ps[w][2 * q][lane] = a2; ps[w][2 * q + 1][lane] = b2;
    }
    __syncthreads();
    {
        const int s = tid >> 5, b = tid & 31;
        float r = 0.0f;
#pragma unroll
        for (int q = 0; q < 8; q++) r += ps[q][s][b];
        int g = s >> 1, hh = s & 1;
        int j = g * 1024 + bj * 2 + hh;
        r += d_g2T[j * 32 + b] + bih[j] + bhh[j];
        gvs[s][b] = r;
    }
    __syncthreads();
    if (tid < 64) {
        int b = tid >> 1, hh = tid & 1;
        int h = bj * 2 + hh;
        float iv = gvs[0 + hh][b], fv = gvs[2 + hh][b];
        float gv = gvs[4 + hh][b], ov = gvs[6 + hh][b];
        float c = d_c[b * 1024 + h];
        float cn = sigf(fv) * c + sigf(iv) * tanhf(gv);
        float hn = sigf(ov) * tanhf(cn);
        d_c[b * 1024 + h] = cn;
        d_h[b * 1024 + h] = hn;
        d_hT[h * 32 + b] = hn;
    }
}

// ---- rec: 640 blocks. h @ [Whh;Wh]^T -> g2T (j<4096) / hWhT ----
__global__ __launch_bounds__(256) void k_rec() {
    __shared__ __align__(16) float ws[1024][8];
    __shared__ float ps[8][8][32];
    const int tid = threadIdx.x, bj = blockIdx.x;
    const float4* wb = (const float4*)(d_WrecB + (size_t)bj * 8192);
#pragma unroll
    for (int i = 0; i < 8; i++) ((float4*)ws)[tid + i * 256] = wb[tid + i * 256];
    __syncthreads();
    const int w = tid >> 5, lane = tid & 31;
    u64 acc[4] = {0ull, 0ull, 0ull, 0ull};
    const float* eb = d_hT + w * 128 * 32 + lane;
#pragma unroll 4
    for (int k = 0; k < 128; k++) {
        u64 ed = dup2f(eb[k * 32]);
        int kk = w * 128 + k;
        ulonglong2 w01 = *(const ulonglong2*)&ws[kk][0];
        ulonglong2 w23 = *(const ulonglong2*)&ws[kk][4];
        ffma2(acc[0], ed, w01.x); ffma2(acc[1], ed, w01.y);
        ffma2(acc[2], ed, w23.x); ffma2(acc[3], ed, w23.y);
    }
#pragma unroll
    for (int q = 0; q < 4; q++) {
        float a2, b2; unpack2(acc[q], a2, b2);
        ps[w][2 * q][lane] = a2; ps[w][2 * q + 1][lane] = b2;
    }
    __syncthreads();
    const int s = tid >> 5, b = tid & 31;
    float r = 0.0f;
#pragma unroll
    for (int q = 0; q < 8; q++) r += ps[q][s][b];
    int j = bj * 8 + s;
    if (j < 4096) d_g2T[j * 32 + b] = r;
    else          d_hWhT[(j - 4096) * 32 + b] = r;
}

// ---- final FC ----
__global__ __launch_bounds__(256) void k_fc(const float* __restrict__ Wfc,
                                            const float* __restrict__ bfc,
                                            float* __restrict__ out) {
    const int b = blockIdx.x, w = threadIdx.x >> 5, lane = threadIdx.x & 31;
    const float* hr = d_h + b * 1024;
    const float* wr = Wfc + w * 1024;
    float s = 0.0f;
    for (int i = lane * 4; i < 1024; i += 128) {
        float4 hv = *(const float4*)&hr[i];
        float4 wv = *(const float4*)&wr[i];
        s = fmaf(hv.x, wv.x, s); s = fmaf(hv.y, wv.y, s);
        s = fmaf(hv.z, wv.z, s); s = fmaf(hv.w, wv.w, s);
    }
#pragma unroll
    for (int off = 16; off; off >>= 1) s += __shfl_xor_sync(0xffffffffu, s, off);
    if (lane == 0) out[b * 8 + w] = s + bfc[w];
}

extern "C" void kernel_launch(void* const* d_in, const int* in_sizes, int n_in,
                              void* d_out, int out_size) {
    const float* x     = (const float*)d_in[0];
    const float* Wx    = (const float*)d_in[1];
    const float* Wh    = (const float*)d_in[2];
    const float* b_att = (const float*)d_in[3];
    const float* v     = (const float*)d_in[4];
    const float* Wih   = (const float*)d_in[5];
    const float* Whh   = (const float*)d_in[6];
    const float* bih   = (const float*)d_in[7];
    const float* bhh   = (const float*)d_in[8];
    const float* Wfc   = (const float*)d_in[9];
    const float* bfc   = (const float*)d_in[10];
    float* out = (float*)d_out;

    static int attr_set = 0;
    if (!attr_set) {
        cudaFuncSetAttribute(k_xe_mma, cudaFuncAttributeMaxDynamicSharedMemorySize, XE_SMEM);
        attr_set = 1;
    }

    k_init<<<512, 256>>>();
    k_prep_rec<<<dim3(32, 160), 256>>>(Whh, Wh);
    k_prep_ih<<<dim3(32, 128), 256>>>(Wih);
    k_cvt_x<<<20480, 256>>>(x);
    k_cvt_w<<<dim3(16, 32), 256>>>(Wx);
    k_xe_mma<<<1280, 256, XE_SMEM>>>();
    for (int t = 0; t < 64; t++) {
        k_attn<<<32, 256>>>(t, x, b_att, v);
        k_gates<<<512, 256>>>(bih, bhh);
        if (t < 63) k_rec<<<640, 256>>>();
    }
    k_fc<<<32, 256>>>(Wfc, bfc, out);
}

// round 12
// speedup vs baseline: 1.5293x; 1.0939x over previous
#include <cuda_runtime.h>
#include <cuda_bf16.h>
#include <math.h>
#include <stdint.h>

typedef unsigned long long u64;

// ---- scratch (static device globals; no allocation) ----
__device__ __align__(16) float d_XE[(size_t)64 * 32 * 10 * 1024];  // 80MB  [t][b][p][h] = [r][h]
__device__ __align__(16) float d_h[32 * 1024];                     // [b][h]
__device__ __align__(16) float d_c[32 * 1024];                     // [b][h]
__device__ __align__(16) float d_hT[1024 * 32];                    // [h][b]
__device__ __align__(16) float d_embT[1024 * 32];                  // [i][b]
__device__ __align__(16) float d_g2T[4096 * 32];                   // [j][b]
__device__ __align__(16) float d_hWhT[1024 * 32];                  // [h][b]
__device__ __align__(16) float d_WrecB[640 * 8192];                // 20MB blocked [tile][k][8]
__device__ __align__(16) float d_WihB[512 * 8192];                 // 16MB blocked [tile][k][8]
__device__ __align__(16) __nv_bfloat16 d_A2[(size_t)20480 * 2048]; // 80MB [r][hi(1024)|lo(1024)]
__device__ __align__(16) __nv_bfloat16 d_B2T[(size_t)2048 * 1024]; // 4MB  [k: hi|lo][h]
// grid barrier: counter and generation on SEPARATE 128B cache lines
__device__ __align__(128) unsigned d_barc[32];
__device__ __align__(128) unsigned d_barg[32];

// ---- f32x2 helpers ----
static __device__ __forceinline__ u64 dup2f(float a) {
    u64 r; asm("mov.b64 %0,{%1,%1};" : "=l"(r) : "f"(a)); return r;
}
static __device__ __forceinline__ void ffma2(u64& d, u64 a, u64 b) {
    asm("fma.rn.f32x2 %0,%1,%2,%0;" : "+l"(d) : "l"(a), "l"(b));
}
static __device__ __forceinline__ void unpack2(u64 v, float& a, float& b) {
    asm("mov.b64 {%0,%1},%2;" : "=f"(a), "=f"(b) : "l"(v));
}
static __device__ __forceinline__ float sigf(float x) { return 1.0f / (1.0f + expf(-x)); }

// ---- mma.sync helpers (base PTX, compute_103-safe) ----
static __device__ __forceinline__ uint32_t s2u(const void* p) {
    uint32_t a;
    asm("{ .reg .u64 t; cvta.to.shared.u64 t, %1; cvt.u32.u64 %0, t; }" : "=r"(a) : "l"(p));
    return a;
}
static __device__ __forceinline__ void ldsm4(uint32_t* r, uint32_t addr) {
    asm volatile("ldmatrix.sync.aligned.m8n8.x4.shared.b16 {%0,%1,%2,%3},[%4];"
                 : "=r"(r[0]), "=r"(r[1]), "=r"(r[2]), "=r"(r[3]) : "r"(addr));
}
static __device__ __forceinline__ void ldsm4t(uint32_t* r, uint32_t addr) {
    asm volatile("ldmatrix.sync.aligned.m8n8.x4.trans.shared.b16 {%0,%1,%2,%3},[%4];"
                 : "=r"(r[0]), "=r"(r[1]), "=r"(r[2]), "=r"(r[3]) : "r"(addr));
}
static __device__ __forceinline__ void mma16816(float* d, const uint32_t* a, const uint32_t* b) {
    asm volatile(
        "mma.sync.aligned.m16n8k16.row.col.f32.bf16.bf16.f32 "
        "{%0,%1,%2,%3},{%4,%5,%6,%7},{%8,%9},{%0,%1,%2,%3};"
        : "+f"(d[0]), "+f"(d[1]), "+f"(d[2]), "+f"(d[3])
        : "r"(a[0]), "r"(a[1]), "r"(a[2]), "r"(a[3]), "r"(b[0]), "r"(b[1]));
}

// ---- software grid barrier (all blocks resident; padded lines + backoff spin) ----
static __device__ __forceinline__ void gridbar() {
    __syncthreads();
    if (threadIdx.x == 0) {
        __threadfence();
        unsigned g = *(volatile unsigned*)&d_barg[0];
        if (atomicAdd(&d_barc[0], 1u) == gridDim.x - 1) {
            d_barc[0] = 0;
            __threadfence();
            *(volatile unsigned*)&d_barg[0] = g + 1;
        } else {
            while (*(volatile unsigned*)&d_barg[0] == g) { __nanosleep(64); }
            __threadfence();
        }
    }
    __syncthreads();
}

// ---- init: zero recurrent state ----
__global__ void k_init() {
    int i = blockIdx.x * blockDim.x + threadIdx.x;   // 512*256 = 131072
    d_g2T[i] = 0.0f;
    if (i < 32 * 1024) { d_c[i] = 0.0f; d_hWhT[i] = 0.0f; }
}

// ---- prep: blocked transpose of [Whh;Wh] -> WrecB[tile][k][s], j = tile*8+s ----
__global__ __launch_bounds__(256) void k_prep_rec(const float* __restrict__ Whh,
                                                  const float* __restrict__ Wh) {
    __shared__ __align__(16) float sm[32][36];
    const int tid = threadIdx.x;
    const int k0 = blockIdx.x * 32, jt = blockIdx.y;
    {
        int r = tid >> 3, c4 = (tid & 7) * 4;
        int j = jt * 32 + r;
        const float* src = (j < 4096) ? (Whh + (size_t)j * 1024) : (Wh + (size_t)(j - 4096) * 1024);
        *(float4*)&sm[r][c4] = *(const float4*)&src[k0 + c4];
    }
    __syncthreads();
    int kk = tid >> 3, s = tid & 7;
#pragma unroll
    for (int bji = 0; bji < 4; bji++) {
        d_WrecB[(size_t)(jt * 4 + bji) * 8192 + (k0 + kk) * 8 + s] = sm[bji * 8 + s][kk];
    }
}

// ---- prep: blocked transpose of Wih -> WihB[tile][k][s], s=(g,hh): j=g*1024+tile*2+hh ----
__global__ __launch_bounds__(256) void k_prep_ih(const float* __restrict__ Wih) {
    __shared__ __align__(16) float sm[32][36];
    const int tid = threadIdx.x;
    const int k0 = blockIdx.x * 32, grp = blockIdx.y;
    {
        int r = tid >> 3, c4 = (tid & 7) * 4;
        int g = r >> 3, bji = (r & 7) >> 1, hh = r & 1;
        int j = g * 1024 + (grp * 4 + bji) * 2 + hh;
        *(float4*)&sm[r][c4] = *(const float4*)&Wih[(size_t)j * 1024 + k0 + c4];
    }
    __syncthreads();
    int kk = tid >> 3, s = tid & 7;
    int g = s >> 1, hh = s & 1;
#pragma unroll
    for (int bji = 0; bji < 4; bji++) {
        d_WihB[(size_t)(grp * 4 + bji) * 8192 + (k0 + kk) * 8 + s] = sm[g * 8 + bji * 2 + hh][kk];
    }
}

// ---- cvt: x -> A2 bf16 hi/lo, gathered to r=(t,b,p) row order ----
__global__ __launch_bounds__(256) void k_cvt_x(const float* __restrict__ x) {
    const int B = blockIdx.x;                       // x-order row (b,t,p)
    const int b = B / 640, rem = B % 640, t = rem / 10, p = rem % 10;
    const size_t r = (size_t)(t * 320 + b * 10 + p);
    const int k4 = threadIdx.x * 4;
    float4 v = *(const float4*)(x + (size_t)B * 1024 + k4);
    __nv_bfloat162 hi01 = __floats2bfloat162_rn(v.x, v.y);
    __nv_bfloat162 hi23 = __floats2bfloat162_rn(v.z, v.w);
    float lx = v.x - __bfloat162float(__low2bfloat16(hi01));
    float ly = v.y - __bfloat162float(__high2bfloat16(hi01));
    float lz = v.z - __bfloat162float(__low2bfloat16(hi23));
    float lw = v.w - __bfloat162float(__high2bfloat16(hi23));
    __nv_bfloat162 lo01 = __floats2bfloat162_rn(lx, ly);
    __nv_bfloat162 lo23 = __floats2bfloat162_rn(lz, lw);
    *(__nv_bfloat162*)(d_A2 + r * 2048 + k4)            = hi01;
    *(__nv_bfloat162*)(d_A2 + r * 2048 + k4 + 2)        = hi23;
    *(__nv_bfloat162*)(d_A2 + r * 2048 + 1024 + k4)     = lo01;
    *(__nv_bfloat162*)(d_A2 + r * 2048 + 1024 + k4 + 2) = lo23;
}

// ---- cvt: Wx -> B2T transposed bf16 hi/lo: B2T[k][h] (hi rows 0-1023, lo 1024-2047) ----
__global__ __launch_bounds__(256) void k_cvt_w(const float* __restrict__ Wx) {
    __shared__ __align__(16) unsigned short s_hi[64][40];
    __shared__ __align__(16) unsigned short s_lo[64][40];
    const int tid = threadIdx.x;
    const int k0 = blockIdx.x * 64, h0 = blockIdx.y * 32;
    {
        int hl = tid >> 3, kq = (tid & 7) * 8;
        const float* src = Wx + (size_t)(h0 + hl) * 1024 + k0 + kq;
        float4 v0 = *(const float4*)src;
        float4 v1 = *(const float4*)(src + 4);
        float vv[8] = {v0.x, v0.y, v0.z, v0.w, v1.x, v1.y, v1.z, v1.w};
#pragma unroll
        for (int j = 0; j < 8; j++) {
            __nv_bfloat16 hb = __float2bfloat16_rn(vv[j]);
            float lo = vv[j] - __bfloat162float(hb);
            __nv_bfloat16 lb = __float2bfloat16_rn(lo);
            s_hi[kq + j][hl] = *(unsigned short*)&hb;
            s_lo[kq + j][hl] = *(unsigned short*)&lb;
        }
    }
    __syncthreads();
    int kl = tid >> 2, hq = (tid & 3) * 8;
    uint4 hv = *(const uint4*)&s_hi[kl][hq];
    uint4 lv = *(const uint4*)&s_lo[kl][hq];
    *(uint4*)(d_B2T + (size_t)(k0 + kl) * 1024 + h0 + hq)        = hv;
    *(uint4*)(d_B2T + (size_t)(1024 + k0 + kl) * 1024 + h0 + hq) = lv;
}

// ---- K0 via mma.sync bf16: XE = A2 x B2T, 3-segment split folded into K=3072 ----
#define SA_BYTES (128 * 144)       // 18432
#define SB_BYTES (64 * 272)        // 17408
#define XE_SMEM (2 * SA_BYTES + 2 * SB_BYTES)   // 71680

static __device__ __forceinline__ void xe_load_chunk(char* dsm, int buf, int c,
                                                     int m0, int n0, int tid) {
    const int seg = c >> 4, kc = (c & 15) << 6;
    const int aoff = (seg == 2) ? 1024 : 0;
    const int boff = (seg == 1) ? 1024 : 0;
    {
        int row = tid >> 1, half = tid & 1;
        const uint4* src = (const uint4*)(d_A2 + (size_t)(m0 + row) * 2048 + aoff + kc + half * 32);
        char* dst = dsm + buf * SA_BYTES + row * 144 + half * 64;
#pragma unroll
        for (int j = 0; j < 4; j++) *(uint4*)(dst + j * 16) = src[j];
    }
    {
        int row = tid >> 2, q = tid & 3;
        const uint4* src = (const uint4*)(d_B2T + (size_t)(boff + kc + row) * 1024 + n0 + q * 32);
        char* dst = dsm + 2 * SA_BYTES + buf * SB_BYTES + row * 272 + q * 64;
#pragma unroll
        for (int j = 0; j < 4; j++) *(uint4*)(dst + j * 16) = src[j];
    }
}

__global__ __launch_bounds__(256, 2) void k_xe_mma() {
    extern __shared__ __align__(16) char dsm[];
    const int tid = threadIdx.x, wid = tid >> 5, lane = tid & 31;
    const int m0 = (blockIdx.x >> 3) * 128, n0 = (blockIdx.x & 7) * 128;
    const int wm = wid >> 2, wn = wid & 3;           // warp tile: 64m x 32n
    const uint32_t smem0 = s2u(dsm);

    float acc[4][4][4];
#pragma unroll
    for (int i = 0; i < 4; i++)
#pragma unroll
        for (int j = 0; j < 4; j++)
#pragma unroll
            for (int q = 0; q < 4; q++) acc[i][j][q] = 0.0f;

    xe_load_chunk(dsm, 0, 0, m0, n0, tid);
    __syncthreads();

    for (int c = 0; c < 48; c++) {
        if (c + 1 < 48) xe_load_chunk(dsm, (c + 1) & 1, c + 1, m0, n0, tid);
        const uint32_t Ab = smem0 + (c & 1) * SA_BYTES;
        const uint32_t Bb = smem0 + 2 * SA_BYTES + (c & 1) * SB_BYTES;
        const uint32_t arow = (lane & 15), ahalf = (lane >> 4) * 8;
#pragma unroll
        for (int ks = 0; ks < 4; ks++) {
            const int kk = ks * 16;
            uint32_t a[4][4];
#pragma unroll
            for (int mt = 0; mt < 4; mt++)
                ldsm4(a[mt], Ab + (wm * 64 + mt * 16 + arow) * 144 + (kk + ahalf) * 2);
            uint32_t bfr[2][4];
#pragma unroll
            for (int pr = 0; pr < 2; pr++)
                ldsm4t(bfr[pr], Bb + (kk + arow) * 272 + (wn * 32 + pr * 16 + ahalf) * 2);
#pragma unroll
            for (int mt = 0; mt < 4; mt++) {
#pragma unroll
                for (int nt = 0; nt < 4; nt++) {
                    mma16816(acc[mt][nt], a[mt], &bfr[nt >> 1][(nt & 1) * 2]);
                }
            }
        }
        __syncthreads();
    }

#pragma unroll
    for (int mt = 0; mt < 4; mt++) {
#pragma unroll
        for (int nt = 0; nt < 4; nt++) {
            int row = m0 + wm * 64 + mt * 16 + (lane >> 2);
            int col = n0 + wn * 32 + nt * 8 + (lane & 3) * 2;
            *(float2*)(d_XE + (size_t)row * 1024 + col) =
                make_float2(acc[mt][nt][0], acc[mt][nt][1]);
            *(float2*)(d_XE + (size_t)(row + 8) * 1024 + col) =
                make_float2(acc[mt][nt][2], acc[mt][nt][3]);
        }
    }
}

// ---- attn(t): 32 blocks x 1024 thr. scores -> softmax(P=10) -> pooled embT ----
__global__ __launch_bounds__(1024) void k_attn(int t, const float* __restrict__ x,
                                               const float* __restrict__ b_att,
                                               const float* __restrict__ v) {
    const int b = blockIdx.x, tid = threadIdx.x;
    __shared__ float sm[10][33];
    __shared__ float al[10];
    const int h = tid;
    const float base = d_hWhT[h * 32 + b] + b_att[h];
    const float vh = v[h];
    const float* xe = d_XE + (size_t)(t * 32 + b) * 10240;
    float ps[10];
#pragma unroll
    for (int p = 0; p < 10; p++) ps[p] = tanhf(xe[p * 1024 + h] + base) * vh;
    const int lane = tid & 31, w = tid >> 5;
#pragma unroll
    for (int p = 0; p < 10; p++) {
        float s = ps[p];
#pragma unroll
        for (int off = 16; off; off >>= 1) s += __shfl_xor_sync(0xffffffffu, s, off);
        if (lane == 0) sm[p][w] = s;
    }
    __syncthreads();
    if (tid < 320) {
        int p = tid >> 5;
        float s = sm[p][lane];
#pragma unroll
        for (int off = 16; off; off >>= 1) s += __shfl_xor_sync(0xffffffffu, s, off);
        if (lane == 0) sm[p][32] = s;
    }
    __syncthreads();
    if (tid == 0) {
        float sc[10], mx = -1e30f;
#pragma unroll
        for (int p = 0; p < 10; p++) { sc[p] = sm[p][32]; mx = fmaxf(mx, sc[p]); }
        float den = 0.0f;
#pragma unroll
        for (int p = 0; p < 10; p++) { sc[p] = expf(sc[p] - mx); den += sc[p]; }
        float inv = 1.0f / den;
#pragma unroll
        for (int p = 0; p < 10; p++) al[p] = sc[p] * inv;
    }
    __syncthreads();
    float a[10];
#pragma unroll
    for (int p = 0; p < 10; p++) a[p] = al[p];
    const float* xb = x + (size_t)(b * 64 + t) * 10240;
    float s = 0.0f;
#pragma unroll
    for (int p = 0; p < 10; p++) s = fmaf(a[p], xb[p * 1024 + tid], s);
    d_embT[tid * 32 + b] = s;
}

// ---- fused step: gates (blocks 0-511) -> gridbar -> rec (640 tiles over 592) ----
__global__ __launch_bounds__(256, 4) void k_step(int dorec,
                                                 const float* __restrict__ bih,
                                                 const float* __restrict__ bhh) {
    __shared__ __align__(16) float ws[1024][8];
    __shared__ float ps[8][8][32];
    __shared__ float gvs[8][32];
    const int tid = threadIdx.x, bid = blockIdx.x;
    const int w = tid >> 5, lane = tid & 31;

    // ---- gates phase ----
    if (bid < 512) {
        const int bj = bid;
        const float4* wb = (const float4*)(d_WihB + (size_t)bj * 8192);
#pragma unroll
        for (int i = 0; i < 8; i++) ((float4*)ws)[tid + i * 256] = wb[tid + i * 256];
        __syncthreads();
        u64 acc[4] = {0ull, 0ull, 0ull, 0ull};
        const float* eb = d_embT + w * 128 * 32 + lane;
#pragma unroll 4
        for (int k = 0; k < 128; k++) {
            u64 ed = dup2f(eb[k * 32]);
            int kk = w * 128 + k;
            ulonglong2 w01 = *(const ulonglong2*)&ws[kk][0];
            ulonglong2 w23 = *(const ulonglong2*)&ws[kk][4];
            ffma2(acc[0], ed, w01.x); ffma2(acc[1], ed, w01.y);
            ffma2(acc[2], ed, w23.x); ffma2(acc[3], ed, w23.y);
        }
#pragma unroll
        for (int q = 0; q < 4; q++) {
            float a2, b2; unpack2(acc[q], a2, b2);
            ps[w][2 * q][lane] = a2; ps[w][2 * q + 1][lane] = b2;
        }
        __syncthreads();
        {
            const int s = w, b = lane;
            float r = 0.0f;
#pragma unroll
            for (int q = 0; q < 8; q++) r += ps[q][s][b];
            int g = s >> 1, hh = s & 1;
            int j = g * 1024 + bj * 2 + hh;
            r += d_g2T[j * 32 + b] + bih[j] + bhh[j];
            gvs[s][b] = r;
        }
        __syncthreads();
        if (tid < 64) {
            int b = tid >> 1, hh = tid & 1;
            int h = bj * 2 + hh;
            float iv = gvs[0 + hh][b], fv = gvs[2 + hh][b];
            float gv = gvs[4 + hh][b], ov = gvs[6 + hh][b];
            float c = d_c[b * 1024 + h];
            float cn = sigf(fv) * c + sigf(iv) * tanhf(gv);
            float hn = sigf(ov) * tanhf(cn);
            d_c[b * 1024 + h] = cn;
            d_h[b * 1024 + h] = hn;
            d_hT[h * 32 + b] = hn;
        }
    }

    // ---- rec phase (next step's g2T / hWhT) ----
    if (dorec) {
        gridbar();
        for (int tl = bid; tl < 640; tl += 592) {
            const float4* wb = (const float4*)(d_WrecB + (size_t)tl * 8192);
#pragma unroll
            for (int i = 0; i < 8; i++) ((float4*)ws)[tid + i * 256] = wb[tid + i * 256];
            __syncthreads();
            u64 acc[4] = {0ull, 0ull, 0ull, 0ull};
            const float* eb = d_hT + w * 128 * 32 + lane;
#pragma unroll 4
            for (int k = 0; k < 128; k++) {
                u64 ed = dup2f(eb[k * 32]);
                int kk = w * 128 + k;
                ulonglong2 w01 = *(const ulonglong2*)&ws[kk][0];
                ulonglong2 w23 = *(const ulonglong2*)&ws[kk][4];
                ffma2(acc[0], ed, w01.x); ffma2(acc[1], ed, w01.y);
                ffma2(acc[2], ed, w23.x); ffma2(acc[3], ed, w23.y);
            }
#pragma unroll
            for (int q = 0; q < 4; q++) {
                float a2, b2; unpack2(acc[q], a2, b2);
                ps[w][2 * q][lane] = a2; ps[w][2 * q + 1][lane] = b2;
            }
            __syncthreads();
            {
                const int s = w, b = lane;
                float r = 0.0f;
#pragma unroll
                for (int q = 0; q < 8; q++) r += ps[q][s][b];
                int j = tl * 8 + s;
                if (j < 4096) d_g2T[j * 32 + b] = r;
                else          d_hWhT[(j - 4096) * 32 + b] = r;
            }
            __syncthreads();
        }
    }
}

// ---- final FC ----
__global__ __launch_bounds__(256) void k_fc(const float* __restrict__ Wfc,
                                            const float* __restrict__ bfc,
                                            float* __restrict__ out) {
    const int b = blockIdx.x, w = threadIdx.x >> 5, lane = threadIdx.x & 31;
    const float* hr = d_h + b * 1024;
    const float* wr = Wfc + w * 1024;
    float s = 0.0f;
    for (int i = lane * 4; i < 1024; i += 128) {
        float4 hv = *(const float4*)&hr[i];
        float4 wv = *(const float4*)&wr[i];
        s = fmaf(hv.x, wv.x, s); s = fmaf(hv.y, wv.y, s);
        s = fmaf(hv.z, wv.z, s); s = fmaf(hv.w, wv.w, s);
    }
#pragma unroll
    for (int off = 16; off; off >>= 1) s += __shfl_xor_sync(0xffffffffu, s, off);
    if (lane == 0) out[b * 8 + w] = s + bfc[w];
}

extern "C" void kernel_launch(void* const* d_in, const int* in_sizes, int n_in,
                              void* d_out, int out_size) {
    const float* x     = (const float*)d_in[0];
    const float* Wx    = (const float*)d_in[1];
    const float* Wh    = (const float*)d_in[2];
    const float* b_att = (const float*)d_in[3];
    const float* v     = (const float*)d_in[4];
    const float* Wih   = (const float*)d_in[5];
    const float* Whh   = (const float*)d_in[6];
    const float* bih   = (const float*)d_in[7];
    const float* bhh   = (const float*)d_in[8];
    const float* Wfc   = (const float*)d_in[9];
    const float* bfc   = (const float*)d_in[10];
    float* out = (float*)d_out;

    static int attr_set = 0;
    if (!attr_set) {
        cudaFuncSetAttribute(k_xe_mma, cudaFuncAttributeMaxDynamicSharedMemorySize, XE_SMEM);
        cudaFuncSetAttribute(k_step, cudaFuncAttributePreferredSharedMemoryCarveout, 100);
        attr_set = 1;
    }

    k_init<<<512, 256>>>();
    k_prep_rec<<<dim3(32, 160), 256>>>(Whh, Wh);
    k_prep_ih<<<dim3(32, 128), 256>>>(Wih);
    k_cvt_x<<<20480, 256>>>(x);
    k_cvt_w<<<dim3(16, 32), 256>>>(Wx);
    k_xe_mma<<<1280, 256, XE_SMEM>>>();
    for (int t = 0; t < 64; t++) {
        k_attn<<<32, 1024>>>(t, x, b_att, v);
        k_step<<<592, 256>>>(t < 63 ? 1 : 0, bih, bhh);
    }
    k_fc<<<32, 256>>>(Wfc, bfc, out);
}